// round 14
// baseline (speedup 1.0000x reference)
#include <cuda_runtime.h>
#include <cuda_bf16.h>
#include <cstdint>

// ---------------------------------------------------------------------------
// Decoder: x[8,512,8,8], style[8,512]
//  5 x { upsample2x -> modconv3x3 -> relu }  then final conv3x3 + bias
// upsample2x + conv3x3(pad1) == per-parity 2x2 conv on the SOURCE grid.
// v9: all upconv layers on mma.sync bf16 (3-product hi/lo split).
//  - activations stored PRE-SPLIT as bf16 hi/lo planes with a zero halo
//    (padded borders never written; __device__ globals are zero-init)
//  - weights staged via cp.async (no register round-trip)
//  - register-pipelined x staging, 3 CTAs/SM target
// ---------------------------------------------------------------------------

#define B_ 8

// ---- static scratch (no allocations allowed) ----
// pre-split padded activation planes (hi/lo bf16), plus fp32 a5 for final conv
__device__ unsigned short g_x0h[B_ * 512 * 10 * 10];
__device__ unsigned short g_x0l[B_ * 512 * 10 * 10];
__device__ unsigned short g_a1h[B_ * 256 * 18 * 18];
__device__ unsigned short g_a1l[B_ * 256 * 18 * 18];
__device__ unsigned short g_a2h[B_ * 128 * 34 * 34];
__device__ unsigned short g_a2l[B_ * 128 * 34 * 34];
__device__ unsigned short g_a3h[B_ * 64 * 66 * 66];
__device__ unsigned short g_a3l[B_ * 64 * 66 * 66];
__device__ unsigned short g_a4h[B_ * 64 * 130 * 130];
__device__ unsigned short g_a4l[B_ * 64 * 130 * 130];
__device__ float g_a5[B_ * 64 * 256 * 256];

// MMA weights per layer: [p][co][k] bf16, k = ci*4 + aa*2 + bb (K = CI*4)
__device__ unsigned short g_wH1[4 * 256 * 2048];
__device__ unsigned short g_wL1[4 * 256 * 2048];
__device__ unsigned short g_wH2[4 * 128 * 1024];
__device__ unsigned short g_wL2[4 * 128 * 1024];
__device__ unsigned short g_wH3[4 * 64 * 512];
__device__ unsigned short g_wL3[4 * 64 * 512];
__device__ unsigned short g_wH4[4 * 64 * 256];
__device__ unsigned short g_wL4[4 * 64 * 256];
__device__ unsigned short g_wH5[4 * 64 * 256];
__device__ unsigned short g_wL5[4 * 64 * 256];

__device__ float g_s1[B_ * 256];
__device__ float g_s2[B_ * 128];
__device__ float g_s3[B_ * 64];
__device__ float g_s4[B_ * 64];
__device__ float g_s5[B_ * 64];

// ---- packed f32x2 helpers (final conv) ----
__device__ __forceinline__ unsigned long long pack2(float lo, float hi) {
    unsigned long long r;
    asm("mov.b64 %0, {%1, %2};" : "=l"(r) : "f"(lo), "f"(hi));
    return r;
}
__device__ __forceinline__ void unpack2(unsigned long long v, float& lo, float& hi) {
    asm("mov.b64 {%0, %1}, %2;" : "=f"(lo), "=f"(hi) : "l"(v));
}
__device__ __forceinline__ void fma2(unsigned long long& d, unsigned long long a,
                                     unsigned long long b) {
    asm("fma.rn.f32x2 %0, %1, %2, %0;" : "+l"(d) : "l"(a), "l"(b));
}

__device__ __forceinline__ uint32_t smem_u32(const void* p) {
    uint32_t a;
    asm("{ .reg .u64 t; cvta.to.shared.u64 t, %1; cvt.u32.u64 %0, t; }"
        : "=r"(a) : "l"(p));
    return a;
}

// bf16 hi/lo split
__device__ __forceinline__ void split_bf(float v, unsigned short& h, unsigned short& l) {
    __nv_bfloat16 hb = __float2bfloat16(v);
    float hf = __bfloat162float(hb);
    __nv_bfloat16 lb = __float2bfloat16(v - hf);
    h = __bfloat16_as_ushort(hb);
    l = __bfloat16_as_ushort(lb);
}

// ---- cp.async ----
__device__ __forceinline__ void cp_async16(void* sdst, const void* gsrc) {
    asm volatile("cp.async.ca.shared.global [%0], [%1], 16;"
                 :: "r"(smem_u32(sdst)), "l"(gsrc) : "memory");
}
__device__ __forceinline__ void cp_commit() {
    asm volatile("cp.async.commit_group;" ::: "memory");
}
__device__ __forceinline__ void cp_wait0() {
    asm volatile("cp.async.wait_group 0;" ::: "memory");
}

// ---- mma / ldmatrix wrappers ----
#define LDSM_X4(r0, r1, r2, r3, addr)                                          \
    asm volatile("ldmatrix.sync.aligned.m8n8.x4.shared.b16 {%0,%1,%2,%3}, [%4];" \
                 : "=r"(r0), "=r"(r1), "=r"(r2), "=r"(r3) : "r"(addr))

__device__ __forceinline__ void mma_bf16(float* d, uint32_t a0, uint32_t a1,
                                         uint32_t a2, uint32_t a3,
                                         uint32_t b0, uint32_t b1) {
    asm volatile(
        "mma.sync.aligned.m16n8k16.row.col.f32.bf16.bf16.f32 "
        "{%0,%1,%2,%3},{%4,%5,%6,%7},{%8,%9},{%0,%1,%2,%3};"
        : "+f"(d[0]), "+f"(d[1]), "+f"(d[2]), "+f"(d[3])
        : "r"(a0), "r"(a1), "r"(a2), "r"(a3), "r"(b0), "r"(b1));
}

// ---------------------------------------------------------------------------
// Fused style FC for all 5 layers
// ---------------------------------------------------------------------------
__global__ void style_all(const float* __restrict__ style,
                          const float* __restrict__ fw1, const float* __restrict__ fb1, float* __restrict__ s1,
                          const float* __restrict__ fw2, const float* __restrict__ fb2, float* __restrict__ s2,
                          const float* __restrict__ fw3, const float* __restrict__ fb3, float* __restrict__ s3,
                          const float* __restrict__ fw4, const float* __restrict__ fb4, float* __restrict__ s4,
                          const float* __restrict__ fw5, const float* __restrict__ fb5, float* __restrict__ s5) {
    int warp = (blockIdx.x * blockDim.x + threadIdx.x) >> 5;
    int lane = threadIdx.x & 31;
    if (warp >= B_ * 576) return;
    int b = warp / 576;
    int o = warp % 576;
    const float *fw, *fb;
    float* s;
    int O, lo;
    if (o < 256)      { fw = fw1; fb = fb1; s = s1; O = 256; lo = o; }
    else if (o < 384) { fw = fw2; fb = fb2; s = s2; O = 128; lo = o - 256; }
    else if (o < 448) { fw = fw3; fb = fb3; s = s3; O = 64;  lo = o - 384; }
    else if (o < 512) { fw = fw4; fb = fb4; s = s4; O = 64;  lo = o - 448; }
    else              { fw = fw5; fb = fb5; s = s5; O = 64;  lo = o - 512; }
    const float* st = style + b * 512;
    const float* wp = fw + (size_t)lo * 512;
    float acc = 0.f;
#pragma unroll 4
    for (int i = lane; i < 512; i += 32) acc += st[i] * wp[i];
#pragma unroll
    for (int off = 16; off > 0; off >>= 1)
        acc += __shfl_down_sync(0xffffffffu, acc, off);
    if (lane == 0) s[b * O + lo] = acc + fb[lo];
}

// ---------------------------------------------------------------------------
// Combined parity weight math: v(py,px,aa,bb) from 3x3 kernel a[ky][kx]
// ---------------------------------------------------------------------------
__device__ __forceinline__ void combine_vals(const float a[3][3], float out[2][2][2][2]) {
    float cc[3][2][2];
#pragma unroll
    for (int ky = 0; ky < 3; ky++) {
        cc[ky][0][0] = a[ky][0];
        cc[ky][0][1] = a[ky][1] + a[ky][2];
        cc[ky][1][0] = a[ky][0] + a[ky][1];
        cc[ky][1][1] = a[ky][2];
    }
#pragma unroll
    for (int py = 0; py < 2; py++)
#pragma unroll
        for (int px = 0; px < 2; px++)
#pragma unroll
            for (int aa = 0; aa < 2; aa++)
#pragma unroll
                for (int bb = 0; bb < 2; bb++) {
                    float v;
                    if (py == 0)
                        v = (aa == 0) ? cc[0][px][bb] : cc[1][px][bb] + cc[2][px][bb];
                    else
                        v = (aa == 0) ? cc[0][px][bb] + cc[1][px][bb] : cc[2][px][bb];
                    out[py][px][aa][bb] = v;
                }
}

// ---------------------------------------------------------------------------
// Build MMA weights for all 5 layers + split input x into padded planes
// ---------------------------------------------------------------------------
__device__ __forceinline__ void build_one(const float* __restrict__ w,
                                          unsigned short* __restrict__ hh,
                                          unsigned short* __restrict__ ll,
                                          int li, int CO, int CI) {
    int co = li / CI, ci = li % CI;
    const float* wp = w + (size_t)li * 9;
    float a[3][3];
#pragma unroll
    for (int ky = 0; ky < 3; ky++)
#pragma unroll
        for (int kx = 0; kx < 3; kx++) a[ky][kx] = wp[ky * 3 + kx];
    float v[2][2][2][2];
    combine_vals(a, v);
    int K = CI * 4;
#pragma unroll
    for (int py = 0; py < 2; py++)
#pragma unroll
        for (int px = 0; px < 2; px++) {
            int p = py * 2 + px;
            size_t base = ((size_t)p * CO + co) * K + ci * 4;
#pragma unroll
            for (int aa = 0; aa < 2; aa++)
#pragma unroll
                for (int bb = 0; bb < 2; bb++) {
                    unsigned short h, l;
                    split_bf(v[py][px][aa][bb], h, l);
                    hh[base + aa * 2 + bb] = h;
                    ll[base + aa * 2 + bb] = l;
                }
        }
}

#define M1 (256 * 512)
#define M2 (128 * 256)
#define M3 (64 * 128)
#define M4 (64 * 64)
#define M5 (64 * 64)
#define XSEG (B_ * 512 * 64)

__global__ void build_all(const float* __restrict__ x,
                          const float* __restrict__ w1, const float* __restrict__ w2,
                          const float* __restrict__ w3, const float* __restrict__ w4,
                          const float* __restrict__ w5,
                          unsigned short* __restrict__ h1, unsigned short* __restrict__ l1,
                          unsigned short* __restrict__ h2, unsigned short* __restrict__ l2,
                          unsigned short* __restrict__ h3, unsigned short* __restrict__ l3,
                          unsigned short* __restrict__ h4, unsigned short* __restrict__ l4,
                          unsigned short* __restrict__ h5, unsigned short* __restrict__ l5,
                          unsigned short* __restrict__ x0h, unsigned short* __restrict__ x0l) {
    int i = blockIdx.x * blockDim.x + threadIdx.x;
    if (i < M1) { build_one(w1, h1, l1, i, 256, 512); return; }
    i -= M1;
    if (i < M2) { build_one(w2, h2, l2, i, 128, 256); return; }
    i -= M2;
    if (i < M3) { build_one(w3, h3, l3, i, 64, 128); return; }
    i -= M3;
    if (i < M4) { build_one(w4, h4, l4, i, 64, 64); return; }
    i -= M4;
    if (i < M5) { build_one(w5, h5, l5, i, 64, 64); return; }
    i -= M5;
    if (i < XSEG) {
        int bc = i >> 6;               // b*512 + ci
        int hw = i & 63;
        int h = hw >> 3, w = hw & 7;
        unsigned short hh, ll;
        split_bf(x[i], hh, ll);
        size_t off = ((size_t)bc * 10 + h + 1) * 10 + (w + 1);
        x0h[off] = hh;
        x0l[off] = ll;
    }
}

// ---------------------------------------------------------------------------
// HMMA upconv. Input: padded pre-split bf16 planes (PHI=HS+2, PWI=WS+2).
// Grid: (WS/8, HS/8, B*4*NG), NG=CO/64. CTA = 8x8 centers, one parity,
// one co-group. GEMM: M=64, N=64, K=CI*4 in chunks of 64.
// Pipeline: cp.async w(next) + LDG x(next) | MMA(cur) | STS x(next) | sync.
// Output: padded split planes (L1-L4) or fp32 (L5).
// ---------------------------------------------------------------------------
template <int CI, int CO, int HS, int WS, bool SPLIT_OUT>
__global__ void __launch_bounds__(256, 3)
upconv_mma(const unsigned short* __restrict__ xhp, const unsigned short* __restrict__ xlp,
           const unsigned short* __restrict__ wH, const unsigned short* __restrict__ wL,
           const float* __restrict__ sc,
           unsigned short* __restrict__ ohp, unsigned short* __restrict__ olp,
           float* __restrict__ dstf) {
    constexpr int PHI = HS + 2, PWI = WS + 2;
    constexpr int PHO = 2 * HS + 2, PWO = 2 * WS + 2;
    constexpr int HO = 2 * HS, WO = 2 * WS;
    constexpr int KT = CI * 4;
    constexpr int KC = 64;
    constexpr int NCH = KT / KC;
    constexpr int SP = KC + 8;              // 72 elems, 144 B rows (16B mult)
    constexpr int NG = CO / 64;
    constexpr int BUF_ELEMS = 4 * 64 * SP;  // xh,xl,wh,wl

    extern __shared__ unsigned short smem[];
    __shared__ float ssc[64];

    const int tid = threadIdx.x;
    const int wid = tid >> 5, lane = tid & 31;

    int z = blockIdx.z;
    const int g = z % NG;
    const int p = (z / NG) & 3;
    const int b = z / (NG * 4);
    const int py = p >> 1, px = p & 1;
    const int m0 = blockIdx.y * 8, n0 = blockIdx.x * 8;
    const int co0 = g * 64;

    if (tid < 64) ssc[tid] = sc[b * CO + co0 + tid];

    const unsigned short* whp = wH + ((size_t)p * CO + co0) * KT;
    const unsigned short* wlp = wL + ((size_t)p * CO + co0) * KT;

    // item decomposition for x staging: 512 items = 2/thread
    // item: ci_l = item>>5; rem = item&31: mr = rem>>2, a=(rem>>1)&1, part=rem&1
    const int it_ci[2] = {tid >> 5, (tid + 256) >> 5};
    const int rem0 = tid & 31;
    const int mr0 = rem0 >> 2, a0 = (rem0 >> 1) & 1, part0 = rem0 & 1;
    // second item has same rem (tid+256 ≡ tid mod 32)
    uint32_t ush[2][9];

    auto ldg_x = [&](int ch) {
#pragma unroll
        for (int it = 0; it < 2; it++) {
            int ci = ch * 16 + it_ci[it];
            const unsigned short* plane = (part0 ? xlp : xhp) +
                ((size_t)(b * CI + ci) * PHI + (m0 + mr0 + py + a0)) * PWI + (n0 + px);
#pragma unroll
            for (int j = 0; j < 9; j++) ush[it][j] = plane[j];
        }
    };
    auto sts_x = [&](int q) {
        unsigned short* base = smem + q * BUF_ELEMS + (part0 ? 64 * SP : 0);
#pragma unroll
        for (int it = 0; it < 2; it++) {
            int ci_l = it_ci[it];
            int e0 = mr0 * 8 * SP + ci_l * 4 + a0 * 2;
#pragma unroll
            for (int nc = 0; nc < 8; nc++) {
                uint32_t v = ush[it][nc] | (ush[it][nc + 1] << 16);
                *(uint32_t*)(base + e0 + nc * SP) = v;
            }
        }
    };
    auto cpa_w = [&](int ch, int q) {
        unsigned short* wbase = smem + q * BUF_ELEMS + 2 * 64 * SP;
        const int k0 = ch * KC;
#pragma unroll
        for (int j = 0; j < 4; j++) {
            int idx = tid + j * 256;          // 0..1023
            int isL = idx >> 9;
            int r = (idx >> 3) & 63;
            int t8 = idx & 7;
            const unsigned short* gsrc = (isL ? wlp : whp) + (size_t)r * KT + k0 + t8 * 8;
            unsigned short* sdst = wbase + isL * 64 * SP + r * SP + t8 * 8;
            cp_async16(sdst, gsrc);
        }
    };

    // warp tile + ldmatrix addresses
    const int mt = wid >> 1;
    const int ch2 = wid & 1;
    const int gq = lane >> 3, gi = lane & 7;
    const int arow = mt * 16 + (gq & 1) * 8 + gi;
    const int acol = (gq >> 1) * 8;
    const int bcol = (gq & 1) * 8;
    const int brow0 = ch2 * 32 + (gq >> 1) * 8 + gi;
    const int brow1 = brow0 + 16;

    uint32_t sb0 = smem_u32(smem);
    uint32_t aH[2], aL[2], bH0[2], bH1[2], bL0[2], bL1[2];
#pragma unroll
    for (int q = 0; q < 2; q++) {
        uint32_t base = sb0 + q * BUF_ELEMS * 2;
        aH[q]  = base + (arow * SP + acol) * 2;
        aL[q]  = base + (64 * SP + arow * SP + acol) * 2;
        bH0[q] = base + (2 * 64 * SP + brow0 * SP + bcol) * 2;
        bH1[q] = base + (2 * 64 * SP + brow1 * SP + bcol) * 2;
        bL0[q] = base + (3 * 64 * SP + brow0 * SP + bcol) * 2;
        bL1[q] = base + (3 * 64 * SP + brow1 * SP + bcol) * 2;
    }

    float d[4][4];
#pragma unroll
    for (int nt = 0; nt < 4; nt++)
#pragma unroll
        for (int j = 0; j < 4; j++) d[nt][j] = 0.f;

    // prologue: buffer 0
    cpa_w(0, 0);
    cp_commit();
    ldg_x(0);
    sts_x(0);
    cp_wait0();
    __syncthreads();

    for (int ch = 0; ch < NCH; ch++) {
        const int cur = ch & 1;
        const int other = cur ^ 1;
        const bool more = (ch + 1 < NCH);
        if (more) {
            cpa_w(ch + 1, other);
            cp_commit();
            ldg_x(ch + 1);
        }
        // ---- MMA over current chunk ----
#pragma unroll
        for (int ks = 0; ks < KC / 16; ks++) {
            const uint32_t koff = ks * 32;
            uint32_t ah0, ah1, ah2, ah3, al0, al1, al2, al3;
            LDSM_X4(ah0, ah1, ah2, ah3, aH[cur] + koff);
            LDSM_X4(al0, al1, al2, al3, aL[cur] + koff);
            uint32_t bh[2][4], bl[2][4];
            LDSM_X4(bh[0][0], bh[0][1], bh[0][2], bh[0][3], bH0[cur] + koff);
            LDSM_X4(bh[1][0], bh[1][1], bh[1][2], bh[1][3], bH1[cur] + koff);
            LDSM_X4(bl[0][0], bl[0][1], bl[0][2], bl[0][3], bL0[cur] + koff);
            LDSM_X4(bl[1][0], bl[1][1], bl[1][2], bl[1][3], bL1[cur] + koff);
#pragma unroll
            for (int nt = 0; nt < 4; nt++) {
                const int q = nt >> 1, lc = nt & 1;
                uint32_t b0h = bh[q][lc * 2], b1h = bh[q][lc * 2 + 1];
                uint32_t b0l = bl[q][lc * 2], b1l = bl[q][lc * 2 + 1];
                mma_bf16(d[nt], ah0, ah1, ah2, ah3, b0h, b1h);  // xh*wh
                mma_bf16(d[nt], ah0, ah1, ah2, ah3, b0l, b1l);  // xh*wl
                mma_bf16(d[nt], al0, al1, al2, al3, b0h, b1h);  // xl*wh
            }
        }
        if (more) {
            sts_x(other);
            cp_wait0();
        }
        __syncthreads();
    }

    // ---- epilogue: scale, relu, store ----
    const int r = lane >> 2;
    const int cp_ = (lane & 3) * 2;
#pragma unroll
    for (int nt = 0; nt < 4; nt++) {
        const int cg0 = ch2 * 32 + nt * 8 + cp_;
#pragma unroll
        for (int half = 0; half < 2; half++) {
            const int m = mt * 16 + r + half * 8;
            const int mr = m >> 3, nc = m & 7;
            const int oy = 2 * (m0 + mr) + py;
            const int ox = 2 * (n0 + nc) + px;
#pragma unroll
            for (int j = 0; j < 2; j++) {
                const int co = cg0 + j;
                float v = d[nt][half * 2 + j] * ssc[co];
                v = v > 0.f ? v : 0.f;
                if (SPLIT_OUT) {
                    unsigned short hh, ll;
                    split_bf(v, hh, ll);
                    size_t off = ((size_t)(b * CO + co0 + co) * PHO + (oy + 1)) * PWO + (ox + 1);
                    ohp[off] = hh;
                    olp[off] = ll;
                } else {
                    dstf[((size_t)(b * CO + co0 + co) * HO + oy) * WO + ox] = v;
                }
            }
        }
    }
}

// ---------------------------------------------------------------------------
// Final plain 3x3 conv: 64 -> 3 channels, 256x256, + bias, smem staged.
// ---------------------------------------------------------------------------
__global__ void __launch_bounds__(256)
final_conv(const float* __restrict__ src, const float* __restrict__ wf,
           const float* __restrict__ bf, float* __restrict__ dst) {
    constexpr int H = 256, W = 256, CI = 64;
    constexpr int TCP = 34;
    constexpr int TR = 34;
    constexpr int CHUNK = 2;
    constexpr int TILE = CHUNK * TR * TCP;
    constexpr int NC = CI / CHUNK;

    __shared__ float ws[3 * 64 * 9];
    __shared__ float xs[2][TILE];

    const int tid = threadIdx.x;
    for (int i = tid; i < 3 * 64 * 9; i += 256) ws[i] = wf[i];

    const int b = blockIdx.z;
    const int tx = tid % 16, ty = tid / 16;
    const int col0 = blockIdx.x * 32;
    const int row0 = blockIdx.y * 32;
    const int px0 = col0 + tx * 2;
    const int py0 = row0 + ty * 2;

    const float* srcb = src + (size_t)b * CI * H * W;

    auto load_chunk = [&](float* buf, int ci0) {
#pragma unroll 2
        for (int idx = tid; idx < TILE; idx += 256) {
            int cc = idx / (TR * TCP);
            int rem = idx % (TR * TCP);
            int r = rem / TCP, c = rem % TCP;
            int iy = row0 - 1 + r;
            int ix = col0 - 1 + c;
            float v = 0.f;
            if (iy >= 0 && iy < H && ix >= 0 && ix < W)
                v = srcb[(size_t)(ci0 + cc) * H * W + iy * W + ix];
            buf[idx] = v;
        }
    };

    unsigned long long acc2[3][2];
#pragma unroll
    for (int c = 0; c < 3; c++)
#pragma unroll
        for (int p = 0; p < 2; p++) acc2[c][p] = 0ull;

    load_chunk(xs[0], 0);
    __syncthreads();

    for (int k = 0; k < NC; k++) {
        const float* cur = xs[k & 1];
        if (k + 1 < NC) load_chunk(xs[(k + 1) & 1], (k + 1) * CHUNK);
        const int ci0 = k * CHUNK;
#pragma unroll
        for (int ccI = 0; ccI < CHUNK; ccI++) {
            const float* tp = cur + ccI * TR * TCP;
            unsigned long long x2[4][3];
#pragma unroll
            for (int r = 0; r < 4; r++) {
                float c0 = tp[(ty * 2 + r) * TCP + tx * 2 + 0];
                float c1 = tp[(ty * 2 + r) * TCP + tx * 2 + 1];
                float c2 = tp[(ty * 2 + r) * TCP + tx * 2 + 2];
                float c3 = tp[(ty * 2 + r) * TCP + tx * 2 + 3];
                x2[r][0] = pack2(c0, c1);
                x2[r][1] = pack2(c1, c2);
                x2[r][2] = pack2(c2, c3);
            }
            const int ci = ci0 + ccI;
#pragma unroll
            for (int co = 0; co < 3; co++) {
                const float* wsp = ws + co * (64 * 9) + ci * 9;
#pragma unroll
                for (int ky = 0; ky < 3; ky++)
#pragma unroll
                    for (int kx = 0; kx < 3; kx++) {
                        float w = wsp[ky * 3 + kx];
                        unsigned long long w2 = pack2(w, w);
#pragma unroll
                        for (int dy = 0; dy < 2; dy++)
                            fma2(acc2[co][dy], w2, x2[dy + ky][kx]);
                    }
            }
        }
        __syncthreads();
    }

#pragma unroll
    for (int co = 0; co < 3; co++) {
        float bias = bf[co];
        float* dp = dst + (((size_t)b * 3 + co) * H) * W;
#pragma unroll
        for (int dy = 0; dy < 2; dy++) {
            float v0, v1;
            unpack2(acc2[co][dy], v0, v1);
            *reinterpret_cast<float2*>(dp + (py0 + dy) * W + px0) =
                make_float2(v0 + bias, v1 + bias);
        }
    }
}

// ---------------------------------------------------------------------------
// launch
// ---------------------------------------------------------------------------
static void* sym(const void* s) {
    void* p = nullptr;
    cudaGetSymbolAddress(&p, s);
    return p;
}

extern "C" void kernel_launch(void* const* d_in, const int* in_sizes, int n_in,
                              void* d_out, int out_size) {
    const float* x     = (const float*)d_in[0];
    const float* style = (const float*)d_in[1];
    const float* w1 = (const float*)d_in[2];
    const float* fw1 = (const float*)d_in[3];
    const float* fb1 = (const float*)d_in[4];
    const float* w2 = (const float*)d_in[5];
    const float* fw2 = (const float*)d_in[6];
    const float* fb2 = (const float*)d_in[7];
    const float* w3 = (const float*)d_in[8];
    const float* fw3 = (const float*)d_in[9];
    const float* fb3 = (const float*)d_in[10];
    const float* w4 = (const float*)d_in[11];
    const float* fw4 = (const float*)d_in[12];
    const float* fb4 = (const float*)d_in[13];
    const float* w5 = (const float*)d_in[14];
    const float* fw5 = (const float*)d_in[15];
    const float* fb5 = (const float*)d_in[16];
    const float* wf = (const float*)d_in[17];
    const float* bf = (const float*)d_in[18];

    unsigned short* x0h = (unsigned short*)sym(g_x0h);
    unsigned short* x0l = (unsigned short*)sym(g_x0l);
    unsigned short* a1h = (unsigned short*)sym(g_a1h);
    unsigned short* a1l = (unsigned short*)sym(g_a1l);
    unsigned short* a2h = (unsigned short*)sym(g_a2h);
    unsigned short* a2l = (unsigned short*)sym(g_a2l);
    unsigned short* a3h = (unsigned short*)sym(g_a3h);
    unsigned short* a3l = (unsigned short*)sym(g_a3l);
    unsigned short* a4h = (unsigned short*)sym(g_a4h);
    unsigned short* a4l = (unsigned short*)sym(g_a4l);
    float* a5 = (float*)sym(g_a5);
    unsigned short* wH1 = (unsigned short*)sym(g_wH1);
    unsigned short* wL1 = (unsigned short*)sym(g_wL1);
    unsigned short* wH2 = (unsigned short*)sym(g_wH2);
    unsigned short* wL2 = (unsigned short*)sym(g_wL2);
    unsigned short* wH3 = (unsigned short*)sym(g_wH3);
    unsigned short* wL3 = (unsigned short*)sym(g_wL3);
    unsigned short* wH4 = (unsigned short*)sym(g_wH4);
    unsigned short* wL4 = (unsigned short*)sym(g_wL4);
    unsigned short* wH5 = (unsigned short*)sym(g_wH5);
    unsigned short* wL5 = (unsigned short*)sym(g_wL5);
    float* s1 = (float*)sym(g_s1);
    float* s2 = (float*)sym(g_s2);
    float* s3 = (float*)sym(g_s3);
    float* s4 = (float*)sym(g_s4);
    float* s5 = (float*)sym(g_s5);

    // dynamic smem: 2 buffers x 4 arrays x 64 x 72 bf16 = 73728 B
    constexpr int MMA_SMEM = 2 * 4 * 64 * 72 * 2;
    cudaFuncSetAttribute(upconv_mma<512, 256, 8, 8, true>,
                         cudaFuncAttributeMaxDynamicSharedMemorySize, MMA_SMEM);
    cudaFuncSetAttribute(upconv_mma<256, 128, 16, 16, true>,
                         cudaFuncAttributeMaxDynamicSharedMemorySize, MMA_SMEM);
    cudaFuncSetAttribute(upconv_mma<128, 64, 32, 32, true>,
                         cudaFuncAttributeMaxDynamicSharedMemorySize, MMA_SMEM);
    cudaFuncSetAttribute(upconv_mma<64, 64, 64, 64, true>,
                         cudaFuncAttributeMaxDynamicSharedMemorySize, MMA_SMEM);
    cudaFuncSetAttribute(upconv_mma<64, 64, 128, 128, false>,
                         cudaFuncAttributeMaxDynamicSharedMemorySize, MMA_SMEM);

    // fused prologue
    {
        int ntot = M1 + M2 + M3 + M4 + M5 + XSEG;
        build_all<<<(ntot + 255) / 256, 256>>>(x, w1, w2, w3, w4, w5,
                                               wH1, wL1, wH2, wL2, wH3, wL3,
                                               wH4, wL4, wH5, wL5, x0h, x0l);
        int warps = B_ * 576;
        style_all<<<(warps * 32 + 255) / 256, 256>>>(style,
                                                     fw1, fb1, s1, fw2, fb2, s2,
                                                     fw3, fb3, s3, fw4, fb4, s4,
                                                     fw5, fb5, s5);
    }

    // L1: 512->256, 8x8 -> 16x16   (128 CTAs)
    upconv_mma<512, 256, 8, 8, true><<<dim3(1, 1, B_ * 4 * 4), 256, MMA_SMEM>>>(
        x0h, x0l, wH1, wL1, s1, a1h, a1l, nullptr);
    // L2: 256->128, 16 -> 32       (256 CTAs)
    upconv_mma<256, 128, 16, 16, true><<<dim3(2, 2, B_ * 4 * 2), 256, MMA_SMEM>>>(
        a1h, a1l, wH2, wL2, s2, a2h, a2l, nullptr);
    // L3: 128->64, 32 -> 64        (512 CTAs)
    upconv_mma<128, 64, 32, 32, true><<<dim3(4, 4, B_ * 4), 256, MMA_SMEM>>>(
        a2h, a2l, wH3, wL3, s3, a3h, a3l, nullptr);
    // L4: 64->64, 64 -> 128        (2048 CTAs)
    upconv_mma<64, 64, 64, 64, true><<<dim3(8, 8, B_ * 4), 256, MMA_SMEM>>>(
        a3h, a3l, wH4, wL4, s4, a4h, a4l, nullptr);
    // L5: 64->64, 128 -> 256       (8192 CTAs)
    upconv_mma<64, 64, 128, 128, false><<<dim3(16, 16, B_ * 4), 256, MMA_SMEM>>>(
        a4h, a4l, wH5, wL5, s5, nullptr, nullptr, a5);

    // final conv 64 -> 3 + bias
    final_conv<<<dim3(8, 8, B_), 256>>>(a5, wf, bf, (float*)d_out);
}

// round 15
// speedup vs baseline: 1.2690x; 1.2690x over previous
#include <cuda_runtime.h>
#include <cuda_bf16.h>
#include <cstdint>

// ---------------------------------------------------------------------------
// Decoder: x[8,512,8,8], style[8,512]
//  5 x { upsample2x -> modconv3x3 -> relu }  then final conv3x3 + bias
// upsample2x + conv3x3(pad1) == per-parity 2x2 conv on the SOURCE grid.
// v10 (= v8 base + fixes): all upconv layers on mma.sync bf16, 3-product
// hi/lo split (D = xh*wh + xh*wl + xl*wh).  K chunks of 64, register-
// pipelined x staging, cp.async weight staging, and MB=2 (128-center CTAs,
// 32x32 warp tiles) on the large layers to cut LDSM traffic 33% and halve
// weight refetch.
// ---------------------------------------------------------------------------

#define B_ 8

// ---- static scratch (no allocations allowed) ----
__device__ float g_a1[B_ * 256 * 16 * 16];
__device__ float g_a2[B_ * 128 * 32 * 32];
__device__ float g_a3[B_ * 64 * 64 * 64];
__device__ float g_a4[B_ * 64 * 128 * 128];
__device__ float g_a5[B_ * 64 * 256 * 256];

// MMA weights per layer: [p][co][k] bf16, k = ci*4 + aa*2 + bb (K = CI*4)
__device__ unsigned short g_wH1[4 * 256 * 2048];
__device__ unsigned short g_wL1[4 * 256 * 2048];
__device__ unsigned short g_wH2[4 * 128 * 1024];
__device__ unsigned short g_wL2[4 * 128 * 1024];
__device__ unsigned short g_wH3[4 * 64 * 512];
__device__ unsigned short g_wL3[4 * 64 * 512];
__device__ unsigned short g_wH4[4 * 64 * 256];
__device__ unsigned short g_wL4[4 * 64 * 256];
__device__ unsigned short g_wH5[4 * 64 * 256];
__device__ unsigned short g_wL5[4 * 64 * 256];

__device__ float g_s1[B_ * 256];
__device__ float g_s2[B_ * 128];
__device__ float g_s3[B_ * 64];
__device__ float g_s4[B_ * 64];
__device__ float g_s5[B_ * 64];

// ---- packed f32x2 helpers (final conv) ----
__device__ __forceinline__ unsigned long long pack2(float lo, float hi) {
    unsigned long long r;
    asm("mov.b64 %0, {%1, %2};" : "=l"(r) : "f"(lo), "f"(hi));
    return r;
}
__device__ __forceinline__ void unpack2(unsigned long long v, float& lo, float& hi) {
    asm("mov.b64 {%0, %1}, %2;" : "=f"(lo), "=f"(hi) : "l"(v));
}
__device__ __forceinline__ void fma2(unsigned long long& d, unsigned long long a,
                                     unsigned long long b) {
    asm("fma.rn.f32x2 %0, %1, %2, %0;" : "+l"(d) : "l"(a), "l"(b));
}

__device__ __forceinline__ uint32_t smem_u32(const void* p) {
    uint32_t a;
    asm("{ .reg .u64 t; cvta.to.shared.u64 t, %1; cvt.u32.u64 %0, t; }"
        : "=r"(a) : "l"(p));
    return a;
}

// bf16 hi/lo split
__device__ __forceinline__ void split_bf(float v, unsigned short& h, unsigned short& l) {
    __nv_bfloat16 hb = __float2bfloat16(v);
    float hf = __bfloat162float(hb);
    __nv_bfloat16 lb = __float2bfloat16(v - hf);
    h = __bfloat16_as_ushort(hb);
    l = __bfloat16_as_ushort(lb);
}

// ---- cp.async ----
__device__ __forceinline__ void cp_async16(void* sdst, const void* gsrc) {
    asm volatile("cp.async.ca.shared.global [%0], [%1], 16;"
                 :: "r"(smem_u32(sdst)), "l"(gsrc) : "memory");
}
__device__ __forceinline__ void cp_commit() {
    asm volatile("cp.async.commit_group;" ::: "memory");
}
__device__ __forceinline__ void cp_wait0() {
    asm volatile("cp.async.wait_group 0;" ::: "memory");
}

// ---- mma / ldmatrix wrappers ----
#define LDSM_X4(r0, r1, r2, r3, addr)                                          \
    asm volatile("ldmatrix.sync.aligned.m8n8.x4.shared.b16 {%0,%1,%2,%3}, [%4];" \
                 : "=r"(r0), "=r"(r1), "=r"(r2), "=r"(r3) : "r"(addr))

__device__ __forceinline__ void mma_bf16(float* d, uint32_t a0, uint32_t a1,
                                         uint32_t a2, uint32_t a3,
                                         uint32_t b0, uint32_t b1) {
    asm volatile(
        "mma.sync.aligned.m16n8k16.row.col.f32.bf16.bf16.f32 "
        "{%0,%1,%2,%3},{%4,%5,%6,%7},{%8,%9},{%0,%1,%2,%3};"
        : "+f"(d[0]), "+f"(d[1]), "+f"(d[2]), "+f"(d[3])
        : "r"(a0), "r"(a1), "r"(a2), "r"(a3), "r"(b0), "r"(b1));
}

// ---------------------------------------------------------------------------
// Fused style FC for all 5 layers
// ---------------------------------------------------------------------------
__global__ void style_all(const float* __restrict__ style,
                          const float* __restrict__ fw1, const float* __restrict__ fb1, float* __restrict__ s1,
                          const float* __restrict__ fw2, const float* __restrict__ fb2, float* __restrict__ s2,
                          const float* __restrict__ fw3, const float* __restrict__ fb3, float* __restrict__ s3,
                          const float* __restrict__ fw4, const float* __restrict__ fb4, float* __restrict__ s4,
                          const float* __restrict__ fw5, const float* __restrict__ fb5, float* __restrict__ s5) {
    int warp = (blockIdx.x * blockDim.x + threadIdx.x) >> 5;
    int lane = threadIdx.x & 31;
    if (warp >= B_ * 576) return;
    int b = warp / 576;
    int o = warp % 576;
    const float *fw, *fb;
    float* s;
    int O, lo;
    if (o < 256)      { fw = fw1; fb = fb1; s = s1; O = 256; lo = o; }
    else if (o < 384) { fw = fw2; fb = fb2; s = s2; O = 128; lo = o - 256; }
    else if (o < 448) { fw = fw3; fb = fb3; s = s3; O = 64;  lo = o - 384; }
    else if (o < 512) { fw = fw4; fb = fb4; s = s4; O = 64;  lo = o - 448; }
    else              { fw = fw5; fb = fb5; s = s5; O = 64;  lo = o - 512; }
    const float* st = style + b * 512;
    const float* wp = fw + (size_t)lo * 512;
    float acc = 0.f;
#pragma unroll 4
    for (int i = lane; i < 512; i += 32) acc += st[i] * wp[i];
#pragma unroll
    for (int off = 16; off > 0; off >>= 1)
        acc += __shfl_down_sync(0xffffffffu, acc, off);
    if (lane == 0) s[b * O + lo] = acc + fb[lo];
}

// ---------------------------------------------------------------------------
// Combined parity weight math: v(py,px,aa,bb) from 3x3 kernel a[ky][kx]
// ---------------------------------------------------------------------------
__device__ __forceinline__ void combine_vals(const float a[3][3], float out[2][2][2][2]) {
    float cc[3][2][2];
#pragma unroll
    for (int ky = 0; ky < 3; ky++) {
        cc[ky][0][0] = a[ky][0];
        cc[ky][0][1] = a[ky][1] + a[ky][2];
        cc[ky][1][0] = a[ky][0] + a[ky][1];
        cc[ky][1][1] = a[ky][2];
    }
#pragma unroll
    for (int py = 0; py < 2; py++)
#pragma unroll
        for (int px = 0; px < 2; px++)
#pragma unroll
            for (int aa = 0; aa < 2; aa++)
#pragma unroll
                for (int bb = 0; bb < 2; bb++) {
                    float v;
                    if (py == 0)
                        v = (aa == 0) ? cc[0][px][bb] : cc[1][px][bb] + cc[2][px][bb];
                    else
                        v = (aa == 0) ? cc[0][px][bb] + cc[1][px][bb] : cc[2][px][bb];
                    out[py][px][aa][bb] = v;
                }
}

// ---------------------------------------------------------------------------
// Build MMA weights for ALL 5 layers: [p][co][k] bf16 hi/lo, k=ci*4+aa*2+bb
// ---------------------------------------------------------------------------
__device__ __forceinline__ void build_one(const float* __restrict__ w,
                                          unsigned short* __restrict__ hh,
                                          unsigned short* __restrict__ ll,
                                          int li, int CO, int CI) {
    int co = li / CI, ci = li % CI;
    const float* wp = w + (size_t)li * 9;
    float a[3][3];
#pragma unroll
    for (int ky = 0; ky < 3; ky++)
#pragma unroll
        for (int kx = 0; kx < 3; kx++) a[ky][kx] = wp[ky * 3 + kx];
    float v[2][2][2][2];
    combine_vals(a, v);
    int K = CI * 4;
#pragma unroll
    for (int py = 0; py < 2; py++)
#pragma unroll
        for (int px = 0; px < 2; px++) {
            int p = py * 2 + px;
            size_t base = ((size_t)p * CO + co) * K + ci * 4;
#pragma unroll
            for (int aa = 0; aa < 2; aa++)
#pragma unroll
                for (int bb = 0; bb < 2; bb++) {
                    unsigned short h, l;
                    split_bf(v[py][px][aa][bb], h, l);
                    hh[base + aa * 2 + bb] = h;
                    ll[base + aa * 2 + bb] = l;
                }
        }
}

#define M1 (256 * 512)
#define M2 (128 * 256)
#define M3 (64 * 128)
#define M4 (64 * 64)
#define M5 (64 * 64)

__global__ void build_all(const float* __restrict__ w1, const float* __restrict__ w2,
                          const float* __restrict__ w3, const float* __restrict__ w4,
                          const float* __restrict__ w5,
                          unsigned short* __restrict__ h1, unsigned short* __restrict__ l1,
                          unsigned short* __restrict__ h2, unsigned short* __restrict__ l2,
                          unsigned short* __restrict__ h3, unsigned short* __restrict__ l3,
                          unsigned short* __restrict__ h4, unsigned short* __restrict__ l4,
                          unsigned short* __restrict__ h5, unsigned short* __restrict__ l5) {
    int i = blockIdx.x * blockDim.x + threadIdx.x;
    if (i < M1) { build_one(w1, h1, l1, i, 256, 512); return; }
    i -= M1;
    if (i < M2) { build_one(w2, h2, l2, i, 128, 256); return; }
    i -= M2;
    if (i < M3) { build_one(w3, h3, l3, i, 64, 128); return; }
    i -= M3;
    if (i < M4) { build_one(w4, h4, l4, i, 64, 64); return; }
    i -= M4;
    if (i < M5) { build_one(w5, h5, l5, i, 64, 64); return; }
}

// ---------------------------------------------------------------------------
// HMMA upconv, software-pipelined K chunks of 64.
// MB = 1: CTA = 8x8 centers (M=64), warp tile 16x32  (as v8, verified)
// MB = 2: CTA = 16x8 centers (M=128), warp tile 32x32 (-33% LDSM/MMA)
// Grid: (WS/8, HS/(8*MB), B*4*NG), NG = CO/64.
// Pipeline per chunk: cp.async w(next) + LDG x(next)->regs | MMA(cur) |
// STS x(next) | sync.   smem: 2 buffers x (x[2*MROWS] + w[128]) rows x 72.
// ---------------------------------------------------------------------------
template <int CI, int CO, int HS, int WS, int MB>
__global__ void __launch_bounds__(256, (MB == 1) ? 3 : 2)
upconv_mma(const float* __restrict__ src,
           const unsigned short* __restrict__ wH, const unsigned short* __restrict__ wL,
           const float* __restrict__ sc, float* __restrict__ dst) {
    constexpr int HO = 2 * HS, WO = 2 * WS;
    constexpr int KT = CI * 4;              // total K
    constexpr int KC = 64;                  // K per chunk (16 ci)
    constexpr int NCH = KT / KC;
    constexpr int SP = KC + 8;              // padded row stride = 72 elems
    constexpr int NG = CO / 64;
    constexpr int MROWS = 64 * MB;          // centers per CTA
    constexpr int BUF_ELEMS = (2 * MROWS + 128) * SP;
    constexpr int ITEMS = 4 * MB;           // x staging items per thread

    extern __shared__ unsigned short smem[];
    __shared__ float ssc[64];

    const int tid = threadIdx.x;
    const int wid = tid >> 5, lane = tid & 31;

    int z = blockIdx.z;
    const int g = z % NG;
    const int p = (z / NG) & 3;
    const int b = z / (NG * 4);
    const int py = p >> 1, px = p & 1;
    const int m0 = blockIdx.y * 8 * MB, n0 = blockIdx.x * 8;
    const int co0 = g * 64;

    if (tid < 64) ssc[tid] = sc[b * CO + co0 + tid];

    const float* sp_b = src + (size_t)b * CI * HS * WS;
    const unsigned short* whp = wH + ((size_t)p * CO + co0) * KT;
    const unsigned short* wlp = wL + ((size_t)p * CO + co0) * KT;

    // warp tile: mt in 0..3 over M, ch2 over co halves
    const int mt = wid >> 1;
    const int ch2 = wid & 1;
    const int gq = lane >> 3, gi = lane & 7;
    const int acol = (gq >> 1) * 8;
    const int bcol = (gq & 1) * 8;
    const int brow0 = ch2 * 32 + (gq >> 1) * 8 + gi;
    const int brow1 = brow0 + 16;

    uint32_t sb0 = smem_u32(smem);
    // per-buffer base addresses
    uint32_t aH[2][MB], aL[2][MB], bH0[2], bH1[2], bL0[2], bL1[2];
#pragma unroll
    for (int q = 0; q < 2; q++) {
        uint32_t base = sb0 + q * BUF_ELEMS * 2;
#pragma unroll
        for (int mb = 0; mb < MB; mb++) {
            int arow = mt * 16 * MB + mb * 16 + (gq & 1) * 8 + gi;
            aH[q][mb] = base + (arow * SP + acol) * 2;
            aL[q][mb] = base + (MROWS * SP + arow * SP + acol) * 2;
        }
        bH0[q] = base + (2 * MROWS * SP + brow0 * SP + bcol) * 2;
        bH1[q] = base + (2 * MROWS * SP + brow1 * SP + bcol) * 2;
        bL0[q] = base + ((2 * MROWS + 64) * SP + brow0 * SP + bcol) * 2;
        bL1[q] = base + ((2 * MROWS + 64) * SP + brow1 * SP + bcol) * 2;
    }

    float d[MB][4][4];
#pragma unroll
    for (int mb = 0; mb < MB; mb++)
#pragma unroll
        for (int nt = 0; nt < 4; nt++)
#pragma unroll
            for (int j = 0; j < 4; j++) d[mb][nt][j] = 0.f;

    float vx[ITEMS][4];

    // ---- LDG x chunk into registers ----
    auto ldg_x = [&](int ch) {
#pragma unroll
        for (int j = 0; j < ITEMS; j++) {
            int idx = tid + j * 256;
            int n = idx >> 4, cil = idx & 15;
            int ci = ch * 16 + cil;
            int mr = n >> 3, nc = n & 7;
            int iy0 = m0 + mr - 1 + py;
            int ix0 = n0 + nc - 1 + px;
            const float* sp = sp_b + (size_t)ci * HS * WS;
            bool y0 = (iy0 >= 0) && (iy0 < HS);
            bool y1 = (iy0 + 1 < HS);
            bool x0 = (ix0 >= 0) && (ix0 < WS);
            bool x1 = (ix0 + 1 < WS);
            vx[j][0] = (y0 && x0) ? sp[iy0 * WS + ix0] : 0.f;
            vx[j][1] = (y0 && x1) ? sp[iy0 * WS + ix0 + 1] : 0.f;
            vx[j][2] = (y1 && x0) ? sp[(iy0 + 1) * WS + ix0] : 0.f;
            vx[j][3] = (y1 && x1) ? sp[(iy0 + 1) * WS + ix0 + 1] : 0.f;
        }
    };
    // ---- split + STS x into buffer q ----
    auto sts_x = [&](int q) {
        unsigned short* base = smem + q * BUF_ELEMS;
        unsigned short* xh = base;
        unsigned short* xl = base + MROWS * SP;
#pragma unroll
        for (int j = 0; j < ITEMS; j++) {
            int idx = tid + j * 256;
            int n = idx >> 4, cil = idx & 15;
            unsigned short h0, l0, h1, l1, h2, l2, h3, l3;
            split_bf(vx[j][0], h0, l0);
            split_bf(vx[j][1], h1, l1);
            split_bf(vx[j][2], h2, l2);
            split_bf(vx[j][3], h3, l3);
            int e = n * SP + cil * 4;
            *(uint2*)(xh + e) = make_uint2((uint32_t)h0 | ((uint32_t)h1 << 16),
                                           (uint32_t)h2 | ((uint32_t)h3 << 16));
            *(uint2*)(xl + e) = make_uint2((uint32_t)l0 | ((uint32_t)l1 << 16),
                                           (uint32_t)l2 | ((uint32_t)l3 << 16));
        }
    };
    // ---- cp.async weight chunk into buffer q ----
    auto cpa_w = [&](int ch, int q) {
        unsigned short* wbase = smem + q * BUF_ELEMS + 2 * MROWS * SP;
        const int k0 = ch * KC;
#pragma unroll
        for (int j = 0; j < 4; j++) {
            int idx = tid + j * 256;          // 0..1023
            int isL = idx >> 9;
            int r = (idx >> 3) & 63;
            int t8 = idx & 7;
            const unsigned short* gsrc = (isL ? wlp : whp) + (size_t)r * KT + k0 + t8 * 8;
            unsigned short* sdst = wbase + isL * 64 * SP + r * SP + t8 * 8;
            cp_async16(sdst, gsrc);
        }
    };

    // prologue: buffer 0
    cpa_w(0, 0);
    cp_commit();
    ldg_x(0);
    sts_x(0);
    cp_wait0();
    __syncthreads();

    for (int ch = 0; ch < NCH; ch++) {
        const int cur = ch & 1;
        const int other = cur ^ 1;
        const bool more = (ch + 1 < NCH);
        if (more) {
            cpa_w(ch + 1, other);
            cp_commit();
            ldg_x(ch + 1);               // LDGs fly during MMA below
        }
        // ---- MMA over current chunk: 4 k-steps ----
#pragma unroll
        for (int ks = 0; ks < KC / 16; ks++) {
            const uint32_t koff = ks * 32;
            uint32_t ah[MB][4], al[MB][4];
#pragma unroll
            for (int mb = 0; mb < MB; mb++) {
                LDSM_X4(ah[mb][0], ah[mb][1], ah[mb][2], ah[mb][3], aH[cur][mb] + koff);
                LDSM_X4(al[mb][0], al[mb][1], al[mb][2], al[mb][3], aL[cur][mb] + koff);
            }
            uint32_t bh[2][4], bl[2][4];
            LDSM_X4(bh[0][0], bh[0][1], bh[0][2], bh[0][3], bH0[cur] + koff);
            LDSM_X4(bh[1][0], bh[1][1], bh[1][2], bh[1][3], bH1[cur] + koff);
            LDSM_X4(bl[0][0], bl[0][1], bl[0][2], bl[0][3], bL0[cur] + koff);
            LDSM_X4(bl[1][0], bl[1][1], bl[1][2], bl[1][3], bL1[cur] + koff);
#pragma unroll
            for (int mb = 0; mb < MB; mb++)
#pragma unroll
                for (int nt = 0; nt < 4; nt++) {
                    const int q = nt >> 1, lc = nt & 1;
                    uint32_t b0h = bh[q][lc * 2], b1h = bh[q][lc * 2 + 1];
                    uint32_t b0l = bl[q][lc * 2], b1l = bl[q][lc * 2 + 1];
                    mma_bf16(d[mb][nt], ah[mb][0], ah[mb][1], ah[mb][2], ah[mb][3], b0h, b1h);
                    mma_bf16(d[mb][nt], ah[mb][0], ah[mb][1], ah[mb][2], ah[mb][3], b0l, b1l);
                    mma_bf16(d[mb][nt], al[mb][0], al[mb][1], al[mb][2], al[mb][3], b0h, b1h);
                }
        }
        if (more) {
            sts_x(other);
            cp_wait0();
        }
        __syncthreads();
    }

    // ---- epilogue: scale, relu, store ----
    const int r = lane >> 2;
    const int cp_ = (lane & 3) * 2;
#pragma unroll
    for (int mb = 0; mb < MB; mb++)
#pragma unroll
        for (int nt = 0; nt < 4; nt++) {
            const int cg0 = ch2 * 32 + nt * 8 + cp_;
#pragma unroll
            for (int half = 0; half < 2; half++) {
                const int m = mt * 16 * MB + mb * 16 + r + half * 8;
                const int mr = m >> 3, nc = m & 7;
                const int oy = 2 * (m0 + mr) + py;
                const int ox = 2 * (n0 + nc) + px;
#pragma unroll
                for (int j = 0; j < 2; j++) {
                    const int co = cg0 + j;
                    float v = d[mb][nt][half * 2 + j] * ssc[co];
                    v = v > 0.f ? v : 0.f;
                    dst[((size_t)(b * CO + co0 + co) * HO + oy) * WO + ox] = v;
                }
            }
        }
}

// ---------------------------------------------------------------------------
// Final plain 3x3 conv: 64 -> 3 channels, 256x256, + bias, smem staged.
// ---------------------------------------------------------------------------
__global__ void __launch_bounds__(256)
final_conv(const float* __restrict__ src, const float* __restrict__ wf,
           const float* __restrict__ bf, float* __restrict__ dst) {
    constexpr int H = 256, W = 256, CI = 64;
    constexpr int TCP = 34;
    constexpr int TR = 34;
    constexpr int CHUNK = 2;
    constexpr int TILE = CHUNK * TR * TCP;
    constexpr int NC = CI / CHUNK;

    __shared__ float ws[3 * 64 * 9];
    __shared__ float xs[2][TILE];

    const int tid = threadIdx.x;
    for (int i = tid; i < 3 * 64 * 9; i += 256) ws[i] = wf[i];

    const int b = blockIdx.z;
    const int tx = tid % 16, ty = tid / 16;
    const int col0 = blockIdx.x * 32;
    const int row0 = blockIdx.y * 32;
    const int px0 = col0 + tx * 2;
    const int py0 = row0 + ty * 2;

    const float* srcb = src + (size_t)b * CI * H * W;

    auto load_chunk = [&](float* buf, int ci0) {
#pragma unroll 2
        for (int idx = tid; idx < TILE; idx += 256) {
            int cc = idx / (TR * TCP);
            int rem = idx % (TR * TCP);
            int r = rem / TCP, c = rem % TCP;
            int iy = row0 - 1 + r;
            int ix = col0 - 1 + c;
            float v = 0.f;
            if (iy >= 0 && iy < H && ix >= 0 && ix < W)
                v = srcb[(size_t)(ci0 + cc) * H * W + iy * W + ix];
            buf[idx] = v;
        }
    };

    unsigned long long acc2[3][2];
#pragma unroll
    for (int c = 0; c < 3; c++)
#pragma unroll
        for (int p = 0; p < 2; p++) acc2[c][p] = 0ull;

    load_chunk(xs[0], 0);
    __syncthreads();

    for (int k = 0; k < NC; k++) {
        const float* cur = xs[k & 1];
        if (k + 1 < NC) load_chunk(xs[(k + 1) & 1], (k + 1) * CHUNK);
        const int ci0 = k * CHUNK;
#pragma unroll
        for (int ccI = 0; ccI < CHUNK; ccI++) {
            const float* tp = cur + ccI * TR * TCP;
            unsigned long long x2[4][3];
#pragma unroll
            for (int r = 0; r < 4; r++) {
                float c0 = tp[(ty * 2 + r) * TCP + tx * 2 + 0];
                float c1 = tp[(ty * 2 + r) * TCP + tx * 2 + 1];
                float c2 = tp[(ty * 2 + r) * TCP + tx * 2 + 2];
                float c3 = tp[(ty * 2 + r) * TCP + tx * 2 + 3];
                x2[r][0] = pack2(c0, c1);
                x2[r][1] = pack2(c1, c2);
                x2[r][2] = pack2(c2, c3);
            }
            const int ci = ci0 + ccI;
#pragma unroll
            for (int co = 0; co < 3; co++) {
                const float* wsp = ws + co * (64 * 9) + ci * 9;
#pragma unroll
                for (int ky = 0; ky < 3; ky++)
#pragma unroll
                    for (int kx = 0; kx < 3; kx++) {
                        float w = wsp[ky * 3 + kx];
                        unsigned long long w2 = pack2(w, w);
#pragma unroll
                        for (int dy = 0; dy < 2; dy++)
                            fma2(acc2[co][dy], w2, x2[dy + ky][kx]);
                    }
            }
        }
        __syncthreads();
    }

#pragma unroll
    for (int co = 0; co < 3; co++) {
        float bias = bf[co];
        float* dp = dst + (((size_t)b * 3 + co) * H) * W;
#pragma unroll
        for (int dy = 0; dy < 2; dy++) {
            float v0, v1;
            unpack2(acc2[co][dy], v0, v1);
            *reinterpret_cast<float2*>(dp + (py0 + dy) * W + px0) =
                make_float2(v0 + bias, v1 + bias);
        }
    }
}

// ---------------------------------------------------------------------------
// launch
// ---------------------------------------------------------------------------
static void* sym(const void* s) {
    void* p = nullptr;
    cudaGetSymbolAddress(&p, s);
    return p;
}

extern "C" void kernel_launch(void* const* d_in, const int* in_sizes, int n_in,
                              void* d_out, int out_size) {
    const float* x     = (const float*)d_in[0];
    const float* style = (const float*)d_in[1];
    const float* w1 = (const float*)d_in[2];
    const float* fw1 = (const float*)d_in[3];
    const float* fb1 = (const float*)d_in[4];
    const float* w2 = (const float*)d_in[5];
    const float* fw2 = (const float*)d_in[6];
    const float* fb2 = (const float*)d_in[7];
    const float* w3 = (const float*)d_in[8];
    const float* fw3 = (const float*)d_in[9];
    const float* fb3 = (const float*)d_in[10];
    const float* w4 = (const float*)d_in[11];
    const float* fw4 = (const float*)d_in[12];
    const float* fb4 = (const float*)d_in[13];
    const float* w5 = (const float*)d_in[14];
    const float* fw5 = (const float*)d_in[15];
    const float* fb5 = (const float*)d_in[16];
    const float* wf = (const float*)d_in[17];
    const float* bf = (const float*)d_in[18];

    float* a1 = (float*)sym(g_a1);
    float* a2 = (float*)sym(g_a2);
    float* a3 = (float*)sym(g_a3);
    float* a4 = (float*)sym(g_a4);
    float* a5 = (float*)sym(g_a5);
    unsigned short* wH1 = (unsigned short*)sym(g_wH1);
    unsigned short* wL1 = (unsigned short*)sym(g_wL1);
    unsigned short* wH2 = (unsigned short*)sym(g_wH2);
    unsigned short* wL2 = (unsigned short*)sym(g_wL2);
    unsigned short* wH3 = (unsigned short*)sym(g_wH3);
    unsigned short* wL3 = (unsigned short*)sym(g_wL3);
    unsigned short* wH4 = (unsigned short*)sym(g_wH4);
    unsigned short* wL4 = (unsigned short*)sym(g_wL4);
    unsigned short* wH5 = (unsigned short*)sym(g_wH5);
    unsigned short* wL5 = (unsigned short*)sym(g_wL5);
    float* s1 = (float*)sym(g_s1);
    float* s2 = (float*)sym(g_s2);
    float* s3 = (float*)sym(g_s3);
    float* s4 = (float*)sym(g_s4);
    float* s5 = (float*)sym(g_s5);

    // dynamic smem: MB=1: (128+128)*72*2*2 = 73728 B; MB=2: (256+128)*72*2*2 = 110592 B
    constexpr int SMEM_MB1 = (2 * 64 + 128) * 72 * 2 * 2;
    constexpr int SMEM_MB2 = (2 * 128 + 128) * 72 * 2 * 2;
    cudaFuncSetAttribute(upconv_mma<512, 256, 8, 8, 1>,
                         cudaFuncAttributeMaxDynamicSharedMemorySize, SMEM_MB1);
    cudaFuncSetAttribute(upconv_mma<256, 128, 16, 16, 1>,
                         cudaFuncAttributeMaxDynamicSharedMemorySize, SMEM_MB1);
    cudaFuncSetAttribute(upconv_mma<128, 64, 32, 32, 2>,
                         cudaFuncAttributeMaxDynamicSharedMemorySize, SMEM_MB2);
    cudaFuncSetAttribute(upconv_mma<64, 64, 64, 64, 2>,
                         cudaFuncAttributeMaxDynamicSharedMemorySize, SMEM_MB2);
    cudaFuncSetAttribute(upconv_mma<64, 64, 128, 128, 2>,
                         cudaFuncAttributeMaxDynamicSharedMemorySize, SMEM_MB2);

    // fused prologue
    {
        int ntot = M1 + M2 + M3 + M4 + M5;
        build_all<<<(ntot + 255) / 256, 256>>>(w1, w2, w3, w4, w5,
                                               wH1, wL1, wH2, wL2, wH3, wL3,
                                               wH4, wL4, wH5, wL5);
        int warps = B_ * 576;
        style_all<<<(warps * 32 + 255) / 256, 256>>>(style,
                                                     fw1, fb1, s1, fw2, fb2, s2,
                                                     fw3, fb3, s3, fw4, fb4, s4,
                                                     fw5, fb5, s5);
    }

    // L1: 512->256, 8x8 -> 16x16   (MB=1, 128 CTAs)
    upconv_mma<512, 256, 8, 8, 1><<<dim3(1, 1, B_ * 4 * 4), 256, SMEM_MB1>>>(x, wH1, wL1, s1, a1);
    // L2: 256->128, 16 -> 32       (MB=1, 256 CTAs)
    upconv_mma<256, 128, 16, 16, 1><<<dim3(2, 2, B_ * 4 * 2), 256, SMEM_MB1>>>(a1, wH2, wL2, s2, a2);
    // L3: 128->64, 32 -> 64        (MB=2, 256 CTAs)
    upconv_mma<128, 64, 32, 32, 2><<<dim3(4, 2, B_ * 4), 256, SMEM_MB2>>>(a2, wH3, wL3, s3, a3);
    // L4: 64->64, 64 -> 128        (MB=2, 1024 CTAs)
    upconv_mma<64, 64, 64, 64, 2><<<dim3(8, 4, B_ * 4), 256, SMEM_MB2>>>(a3, wH4, wL4, s4, a4);
    // L5: 64->64, 128 -> 256       (MB=2, 4096 CTAs)
    upconv_mma<64, 64, 128, 128, 2><<<dim3(16, 8, B_ * 4), 256, SMEM_MB2>>>(a4, wH5, wL5, s5, a5);

    // final conv 64 -> 3 + bias
    final_conv<<<dim3(8, 8, B_), 256>>>(a5, wf, bf, (float*)d_out);
}

// round 16
// speedup vs baseline: 1.7613x; 1.3879x over previous
#include <cuda_runtime.h>
#include <cuda_bf16.h>
#include <cstdint>

// ---------------------------------------------------------------------------
// Decoder: x[8,512,8,8], style[8,512]
//  5 x { upsample2x -> modconv3x3 -> relu }  then final conv3x3 + bias
// upsample2x + conv3x3(pad1) == per-parity 2x2 conv on the SOURCE grid.
// v11: v10 with COALESCED x staging (n-major item map: consecutive lanes
// read consecutive spatial columns, not consecutive channels). Everything
// else identical: mma.sync bf16 3-product hi/lo split, K chunks of 64,
// register-pipelined x staging, cp.async weights, MB=2 on large layers.
// ---------------------------------------------------------------------------

#define B_ 8

// ---- static scratch (no allocations allowed) ----
__device__ float g_a1[B_ * 256 * 16 * 16];
__device__ float g_a2[B_ * 128 * 32 * 32];
__device__ float g_a3[B_ * 64 * 64 * 64];
__device__ float g_a4[B_ * 64 * 128 * 128];
__device__ float g_a5[B_ * 64 * 256 * 256];

// MMA weights per layer: [p][co][k] bf16, k = ci*4 + aa*2 + bb (K = CI*4)
__device__ unsigned short g_wH1[4 * 256 * 2048];
__device__ unsigned short g_wL1[4 * 256 * 2048];
__device__ unsigned short g_wH2[4 * 128 * 1024];
__device__ unsigned short g_wL2[4 * 128 * 1024];
__device__ unsigned short g_wH3[4 * 64 * 512];
__device__ unsigned short g_wL3[4 * 64 * 512];
__device__ unsigned short g_wH4[4 * 64 * 256];
__device__ unsigned short g_wL4[4 * 64 * 256];
__device__ unsigned short g_wH5[4 * 64 * 256];
__device__ unsigned short g_wL5[4 * 64 * 256];

__device__ float g_s1[B_ * 256];
__device__ float g_s2[B_ * 128];
__device__ float g_s3[B_ * 64];
__device__ float g_s4[B_ * 64];
__device__ float g_s5[B_ * 64];

// ---- packed f32x2 helpers (final conv) ----
__device__ __forceinline__ unsigned long long pack2(float lo, float hi) {
    unsigned long long r;
    asm("mov.b64 %0, {%1, %2};" : "=l"(r) : "f"(lo), "f"(hi));
    return r;
}
__device__ __forceinline__ void unpack2(unsigned long long v, float& lo, float& hi) {
    asm("mov.b64 {%0, %1}, %2;" : "=f"(lo), "=f"(hi) : "l"(v));
}
__device__ __forceinline__ void fma2(unsigned long long& d, unsigned long long a,
                                     unsigned long long b) {
    asm("fma.rn.f32x2 %0, %1, %2, %0;" : "+l"(d) : "l"(a), "l"(b));
}

__device__ __forceinline__ uint32_t smem_u32(const void* p) {
    uint32_t a;
    asm("{ .reg .u64 t; cvta.to.shared.u64 t, %1; cvt.u32.u64 %0, t; }"
        : "=r"(a) : "l"(p));
    return a;
}

// bf16 hi/lo split
__device__ __forceinline__ void split_bf(float v, unsigned short& h, unsigned short& l) {
    __nv_bfloat16 hb = __float2bfloat16(v);
    float hf = __bfloat162float(hb);
    __nv_bfloat16 lb = __float2bfloat16(v - hf);
    h = __bfloat16_as_ushort(hb);
    l = __bfloat16_as_ushort(lb);
}

// ---- cp.async ----
__device__ __forceinline__ void cp_async16(void* sdst, const void* gsrc) {
    asm volatile("cp.async.ca.shared.global [%0], [%1], 16;"
                 :: "r"(smem_u32(sdst)), "l"(gsrc) : "memory");
}
__device__ __forceinline__ void cp_commit() {
    asm volatile("cp.async.commit_group;" ::: "memory");
}
__device__ __forceinline__ void cp_wait0() {
    asm volatile("cp.async.wait_group 0;" ::: "memory");
}

// ---- mma / ldmatrix wrappers ----
#define LDSM_X4(r0, r1, r2, r3, addr)                                          \
    asm volatile("ldmatrix.sync.aligned.m8n8.x4.shared.b16 {%0,%1,%2,%3}, [%4];" \
                 : "=r"(r0), "=r"(r1), "=r"(r2), "=r"(r3) : "r"(addr))

__device__ __forceinline__ void mma_bf16(float* d, uint32_t a0, uint32_t a1,
                                         uint32_t a2, uint32_t a3,
                                         uint32_t b0, uint32_t b1) {
    asm volatile(
        "mma.sync.aligned.m16n8k16.row.col.f32.bf16.bf16.f32 "
        "{%0,%1,%2,%3},{%4,%5,%6,%7},{%8,%9},{%0,%1,%2,%3};"
        : "+f"(d[0]), "+f"(d[1]), "+f"(d[2]), "+f"(d[3])
        : "r"(a0), "r"(a1), "r"(a2), "r"(a3), "r"(b0), "r"(b1));
}

// ---------------------------------------------------------------------------
// Fused style FC for all 5 layers
// ---------------------------------------------------------------------------
__global__ void style_all(const float* __restrict__ style,
                          const float* __restrict__ fw1, const float* __restrict__ fb1, float* __restrict__ s1,
                          const float* __restrict__ fw2, const float* __restrict__ fb2, float* __restrict__ s2,
                          const float* __restrict__ fw3, const float* __restrict__ fb3, float* __restrict__ s3,
                          const float* __restrict__ fw4, const float* __restrict__ fb4, float* __restrict__ s4,
                          const float* __restrict__ fw5, const float* __restrict__ fb5, float* __restrict__ s5) {
    int warp = (blockIdx.x * blockDim.x + threadIdx.x) >> 5;
    int lane = threadIdx.x & 31;
    if (warp >= B_ * 576) return;
    int b = warp / 576;
    int o = warp % 576;
    const float *fw, *fb;
    float* s;
    int O, lo;
    if (o < 256)      { fw = fw1; fb = fb1; s = s1; O = 256; lo = o; }
    else if (o < 384) { fw = fw2; fb = fb2; s = s2; O = 128; lo = o - 256; }
    else if (o < 448) { fw = fw3; fb = fb3; s = s3; O = 64;  lo = o - 384; }
    else if (o < 512) { fw = fw4; fb = fb4; s = s4; O = 64;  lo = o - 448; }
    else              { fw = fw5; fb = fb5; s = s5; O = 64;  lo = o - 512; }
    const float* st = style + b * 512;
    const float* wp = fw + (size_t)lo * 512;
    float acc = 0.f;
#pragma unroll 4
    for (int i = lane; i < 512; i += 32) acc += st[i] * wp[i];
#pragma unroll
    for (int off = 16; off > 0; off >>= 1)
        acc += __shfl_down_sync(0xffffffffu, acc, off);
    if (lane == 0) s[b * O + lo] = acc + fb[lo];
}

// ---------------------------------------------------------------------------
// Combined parity weight math: v(py,px,aa,bb) from 3x3 kernel a[ky][kx]
// ---------------------------------------------------------------------------
__device__ __forceinline__ void combine_vals(const float a[3][3], float out[2][2][2][2]) {
    float cc[3][2][2];
#pragma unroll
    for (int ky = 0; ky < 3; ky++) {
        cc[ky][0][0] = a[ky][0];
        cc[ky][0][1] = a[ky][1] + a[ky][2];
        cc[ky][1][0] = a[ky][0] + a[ky][1];
        cc[ky][1][1] = a[ky][2];
    }
#pragma unroll
    for (int py = 0; py < 2; py++)
#pragma unroll
        for (int px = 0; px < 2; px++)
#pragma unroll
            for (int aa = 0; aa < 2; aa++)
#pragma unroll
                for (int bb = 0; bb < 2; bb++) {
                    float v;
                    if (py == 0)
                        v = (aa == 0) ? cc[0][px][bb] : cc[1][px][bb] + cc[2][px][bb];
                    else
                        v = (aa == 0) ? cc[0][px][bb] + cc[1][px][bb] : cc[2][px][bb];
                    out[py][px][aa][bb] = v;
                }
}

// ---------------------------------------------------------------------------
// Build MMA weights for ALL 5 layers: [p][co][k] bf16 hi/lo, k=ci*4+aa*2+bb
// ---------------------------------------------------------------------------
__device__ __forceinline__ void build_one(const float* __restrict__ w,
                                          unsigned short* __restrict__ hh,
                                          unsigned short* __restrict__ ll,
                                          int li, int CO, int CI) {
    int co = li / CI, ci = li % CI;
    const float* wp = w + (size_t)li * 9;
    float a[3][3];
#pragma unroll
    for (int ky = 0; ky < 3; ky++)
#pragma unroll
        for (int kx = 0; kx < 3; kx++) a[ky][kx] = wp[ky * 3 + kx];
    float v[2][2][2][2];
    combine_vals(a, v);
    int K = CI * 4;
#pragma unroll
    for (int py = 0; py < 2; py++)
#pragma unroll
        for (int px = 0; px < 2; px++) {
            int p = py * 2 + px;
            size_t base = ((size_t)p * CO + co) * K + ci * 4;
#pragma unroll
            for (int aa = 0; aa < 2; aa++)
#pragma unroll
                for (int bb = 0; bb < 2; bb++) {
                    unsigned short h, l;
                    split_bf(v[py][px][aa][bb], h, l);
                    hh[base + aa * 2 + bb] = h;
                    ll[base + aa * 2 + bb] = l;
                }
        }
}

#define M1 (256 * 512)
#define M2 (128 * 256)
#define M3 (64 * 128)
#define M4 (64 * 64)
#define M5 (64 * 64)

__global__ void build_all(const float* __restrict__ w1, const float* __restrict__ w2,
                          const float* __restrict__ w3, const float* __restrict__ w4,
                          const float* __restrict__ w5,
                          unsigned short* __restrict__ h1, unsigned short* __restrict__ l1,
                          unsigned short* __restrict__ h2, unsigned short* __restrict__ l2,
                          unsigned short* __restrict__ h3, unsigned short* __restrict__ l3,
                          unsigned short* __restrict__ h4, unsigned short* __restrict__ l4,
                          unsigned short* __restrict__ h5, unsigned short* __restrict__ l5) {
    int i = blockIdx.x * blockDim.x + threadIdx.x;
    if (i < M1) { build_one(w1, h1, l1, i, 256, 512); return; }
    i -= M1;
    if (i < M2) { build_one(w2, h2, l2, i, 128, 256); return; }
    i -= M2;
    if (i < M3) { build_one(w3, h3, l3, i, 64, 128); return; }
    i -= M3;
    if (i < M4) { build_one(w4, h4, l4, i, 64, 64); return; }
    i -= M4;
    if (i < M5) { build_one(w5, h5, l5, i, 64, 64); return; }
}

// ---------------------------------------------------------------------------
// HMMA upconv, software-pipelined K chunks of 64.
// MB = 1: CTA = 8x8 centers (M=64), warp tile 16x32
// MB = 2: CTA = 16x8 centers (M=128), warp tile 32x32
// Grid: (WS/8, HS/(8*MB), B*4*NG), NG = CO/64.
// x staging is N-MAJOR: item idx -> n = idx % MROWS (consecutive lanes =
// consecutive spatial cols = coalesced LDG), cil = idx / MROWS.
// Pipeline per chunk: cp.async w(next) + LDG x(next)->regs | MMA(cur) |
// STS x(next) | sync.
// ---------------------------------------------------------------------------
template <int CI, int CO, int HS, int WS, int MB>
__global__ void __launch_bounds__(256, (MB == 1) ? 3 : 2)
upconv_mma(const float* __restrict__ src,
           const unsigned short* __restrict__ wH, const unsigned short* __restrict__ wL,
           const float* __restrict__ sc, float* __restrict__ dst) {
    constexpr int HO = 2 * HS, WO = 2 * WS;
    constexpr int KT = CI * 4;              // total K
    constexpr int KC = 64;                  // K per chunk (16 ci)
    constexpr int NCH = KT / KC;
    constexpr int SP = KC + 8;              // padded row stride = 72 elems
    constexpr int NG = CO / 64;
    constexpr int MROWS = 64 * MB;          // centers per CTA
    constexpr int BUF_ELEMS = (2 * MROWS + 128) * SP;
    constexpr int ITEMS = 4 * MB;           // x staging items per thread

    extern __shared__ unsigned short smem[];
    __shared__ float ssc[64];

    const int tid = threadIdx.x;
    const int wid = tid >> 5, lane = tid & 31;

    int z = blockIdx.z;
    const int g = z % NG;
    const int p = (z / NG) & 3;
    const int b = z / (NG * 4);
    const int py = p >> 1, px = p & 1;
    const int m0 = blockIdx.y * 8 * MB, n0 = blockIdx.x * 8;
    const int co0 = g * 64;

    if (tid < 64) ssc[tid] = sc[b * CO + co0 + tid];

    const float* sp_b = src + (size_t)b * CI * HS * WS;
    const unsigned short* whp = wH + ((size_t)p * CO + co0) * KT;
    const unsigned short* wlp = wL + ((size_t)p * CO + co0) * KT;

    // n-major item decomposition (fixed per thread across chunks)
    int it_n[ITEMS], it_cil[ITEMS];
#pragma unroll
    for (int j = 0; j < ITEMS; j++) {
        int idx = tid + j * 256;
        it_n[j] = idx % MROWS;
        it_cil[j] = idx / MROWS;
    }

    // warp tile: mt in 0..3 over M, ch2 over co halves
    const int mt = wid >> 1;
    const int ch2 = wid & 1;
    const int gq = lane >> 3, gi = lane & 7;
    const int acol = (gq >> 1) * 8;
    const int bcol = (gq & 1) * 8;
    const int brow0 = ch2 * 32 + (gq >> 1) * 8 + gi;
    const int brow1 = brow0 + 16;

    uint32_t sb0 = smem_u32(smem);
    uint32_t aH[2][MB], aL[2][MB], bH0[2], bH1[2], bL0[2], bL1[2];
#pragma unroll
    for (int q = 0; q < 2; q++) {
        uint32_t base = sb0 + q * BUF_ELEMS * 2;
#pragma unroll
        for (int mb = 0; mb < MB; mb++) {
            int arow = mt * 16 * MB + mb * 16 + (gq & 1) * 8 + gi;
            aH[q][mb] = base + (arow * SP + acol) * 2;
            aL[q][mb] = base + (MROWS * SP + arow * SP + acol) * 2;
        }
        bH0[q] = base + (2 * MROWS * SP + brow0 * SP + bcol) * 2;
        bH1[q] = base + (2 * MROWS * SP + brow1 * SP + bcol) * 2;
        bL0[q] = base + ((2 * MROWS + 64) * SP + brow0 * SP + bcol) * 2;
        bL1[q] = base + ((2 * MROWS + 64) * SP + brow1 * SP + bcol) * 2;
    }

    float d[MB][4][4];
#pragma unroll
    for (int mb = 0; mb < MB; mb++)
#pragma unroll
        for (int nt = 0; nt < 4; nt++)
#pragma unroll
            for (int j = 0; j < 4; j++) d[mb][nt][j] = 0.f;

    float vx[ITEMS][4];

    // ---- LDG x chunk into registers (coalesced: lanes sweep n) ----
    auto ldg_x = [&](int ch) {
#pragma unroll
        for (int j = 0; j < ITEMS; j++) {
            int n = it_n[j];
            int ci = ch * 16 + it_cil[j];
            int mr = n >> 3, nc = n & 7;
            int iy0 = m0 + mr - 1 + py;
            int ix0 = n0 + nc - 1 + px;
            const float* sp = sp_b + (size_t)ci * HS * WS;
            bool y0 = (iy0 >= 0) && (iy0 < HS);
            bool y1 = (iy0 + 1 < HS);
            bool x0 = (ix0 >= 0) && (ix0 < WS);
            bool x1 = (ix0 + 1 < WS);
            vx[j][0] = (y0 && x0) ? sp[iy0 * WS + ix0] : 0.f;
            vx[j][1] = (y0 && x1) ? sp[iy0 * WS + ix0 + 1] : 0.f;
            vx[j][2] = (y1 && x0) ? sp[(iy0 + 1) * WS + ix0] : 0.f;
            vx[j][3] = (y1 && x1) ? sp[(iy0 + 1) * WS + ix0 + 1] : 0.f;
        }
    };
    // ---- split + STS x into buffer q ----
    auto sts_x = [&](int q) {
        unsigned short* base = smem + q * BUF_ELEMS;
        unsigned short* xh = base;
        unsigned short* xl = base + MROWS * SP;
#pragma unroll
        for (int j = 0; j < ITEMS; j++) {
            int n = it_n[j];
            int cil = it_cil[j];
            unsigned short h0, l0, h1, l1, h2, l2, h3, l3;
            split_bf(vx[j][0], h0, l0);
            split_bf(vx[j][1], h1, l1);
            split_bf(vx[j][2], h2, l2);
            split_bf(vx[j][3], h3, l3);
            int e = n * SP + cil * 4;
            *(uint2*)(xh + e) = make_uint2((uint32_t)h0 | ((uint32_t)h1 << 16),
                                           (uint32_t)h2 | ((uint32_t)h3 << 16));
            *(uint2*)(xl + e) = make_uint2((uint32_t)l0 | ((uint32_t)l1 << 16),
                                           (uint32_t)l2 | ((uint32_t)l3 << 16));
        }
    };
    // ---- cp.async weight chunk into buffer q ----
    auto cpa_w = [&](int ch, int q) {
        unsigned short* wbase = smem + q * BUF_ELEMS + 2 * MROWS * SP;
        const int k0 = ch * KC;
#pragma unroll
        for (int j = 0; j < 4; j++) {
            int idx = tid + j * 256;          // 0..1023
            int isL = idx >> 9;
            int r = (idx >> 3) & 63;
            int t8 = idx & 7;
            const unsigned short* gsrc = (isL ? wlp : whp) + (size_t)r * KT + k0 + t8 * 8;
            unsigned short* sdst = wbase + isL * 64 * SP + r * SP + t8 * 8;
            cp_async16(sdst, gsrc);
        }
    };

    // prologue: buffer 0
    cpa_w(0, 0);
    cp_commit();
    ldg_x(0);
    sts_x(0);
    cp_wait0();
    __syncthreads();

    for (int ch = 0; ch < NCH; ch++) {
        const int cur = ch & 1;
        const int other = cur ^ 1;
        const bool more = (ch + 1 < NCH);
        if (more) {
            cpa_w(ch + 1, other);
            cp_commit();
            ldg_x(ch + 1);               // LDGs fly during MMA below
        }
        // ---- MMA over current chunk: 4 k-steps ----
#pragma unroll
        for (int ks = 0; ks < KC / 16; ks++) {
            const uint32_t koff = ks * 32;
            uint32_t ah[MB][4], al[MB][4];
#pragma unroll
            for (int mb = 0; mb < MB; mb++) {
                LDSM_X4(ah[mb][0], ah[mb][1], ah[mb][2], ah[mb][3], aH[cur][mb] + koff);
                LDSM_X4(al[mb][0], al[mb][1], al[mb][2], al[mb][3], aL[cur][mb] + koff);
            }
            uint32_t bh[2][4], bl[2][4];
            LDSM_X4(bh[0][0], bh[0][1], bh[0][2], bh[0][3], bH0[cur] + koff);
            LDSM_X4(bh[1][0], bh[1][1], bh[1][2], bh[1][3], bH1[cur] + koff);
            LDSM_X4(bl[0][0], bl[0][1], bl[0][2], bl[0][3], bL0[cur] + koff);
            LDSM_X4(bl[1][0], bl[1][1], bl[1][2], bl[1][3], bL1[cur] + koff);
#pragma unroll
            for (int mb = 0; mb < MB; mb++)
#pragma unroll
                for (int nt = 0; nt < 4; nt++) {
                    const int q = nt >> 1, lc = nt & 1;
                    uint32_t b0h = bh[q][lc * 2], b1h = bh[q][lc * 2 + 1];
                    uint32_t b0l = bl[q][lc * 2], b1l = bl[q][lc * 2 + 1];
                    mma_bf16(d[mb][nt], ah[mb][0], ah[mb][1], ah[mb][2], ah[mb][3], b0h, b1h);
                    mma_bf16(d[mb][nt], ah[mb][0], ah[mb][1], ah[mb][2], ah[mb][3], b0l, b1l);
                    mma_bf16(d[mb][nt], al[mb][0], al[mb][1], al[mb][2], al[mb][3], b0h, b1h);
                }
        }
        if (more) {
            sts_x(other);
            cp_wait0();
        }
        __syncthreads();
    }

    // ---- epilogue: scale, relu, store ----
    const int r = lane >> 2;
    const int cp_ = (lane & 3) * 2;
#pragma unroll
    for (int mb = 0; mb < MB; mb++)
#pragma unroll
        for (int nt = 0; nt < 4; nt++) {
            const int cg0 = ch2 * 32 + nt * 8 + cp_;
#pragma unroll
            for (int half = 0; half < 2; half++) {
                const int m = mt * 16 * MB + mb * 16 + r + half * 8;
                const int mr = m >> 3, nc = m & 7;
                const int oy = 2 * (m0 + mr) + py;
                const int ox = 2 * (n0 + nc) + px;
#pragma unroll
                for (int j = 0; j < 2; j++) {
                    const int co = cg0 + j;
                    float v = d[mb][nt][half * 2 + j] * ssc[co];
                    v = v > 0.f ? v : 0.f;
                    dst[((size_t)(b * CO + co0 + co) * HO + oy) * WO + ox] = v;
                }
            }
        }
}

// ---------------------------------------------------------------------------
// Final plain 3x3 conv: 64 -> 3 channels, 256x256, + bias, smem staged.
// ---------------------------------------------------------------------------
__global__ void __launch_bounds__(256)
final_conv(const float* __restrict__ src, const float* __restrict__ wf,
           const float* __restrict__ bf, float* __restrict__ dst) {
    constexpr int H = 256, W = 256, CI = 64;
    constexpr int TCP = 34;
    constexpr int TR = 34;
    constexpr int CHUNK = 2;
    constexpr int TILE = CHUNK * TR * TCP;
    constexpr int NC = CI / CHUNK;

    __shared__ float ws[3 * 64 * 9];
    __shared__ float xs[2][TILE];

    const int tid = threadIdx.x;
    for (int i = tid; i < 3 * 64 * 9; i += 256) ws[i] = wf[i];

    const int b = blockIdx.z;
    const int tx = tid % 16, ty = tid / 16;
    const int col0 = blockIdx.x * 32;
    const int row0 = blockIdx.y * 32;
    const int px0 = col0 + tx * 2;
    const int py0 = row0 + ty * 2;

    const float* srcb = src + (size_t)b * CI * H * W;

    auto load_chunk = [&](float* buf, int ci0) {
#pragma unroll 2
        for (int idx = tid; idx < TILE; idx += 256) {
            int cc = idx / (TR * TCP);
            int rem = idx % (TR * TCP);
            int r = rem / TCP, c = rem % TCP;
            int iy = row0 - 1 + r;
            int ix = col0 - 1 + c;
            float v = 0.f;
            if (iy >= 0 && iy < H && ix >= 0 && ix < W)
                v = srcb[(size_t)(ci0 + cc) * H * W + iy * W + ix];
            buf[idx] = v;
        }
    };

    unsigned long long acc2[3][2];
#pragma unroll
    for (int c = 0; c < 3; c++)
#pragma unroll
        for (int p = 0; p < 2; p++) acc2[c][p] = 0ull;

    load_chunk(xs[0], 0);
    __syncthreads();

    for (int k = 0; k < NC; k++) {
        const float* cur = xs[k & 1];
        if (k + 1 < NC) load_chunk(xs[(k + 1) & 1], (k + 1) * CHUNK);
        const int ci0 = k * CHUNK;
#pragma unroll
        for (int ccI = 0; ccI < CHUNK; ccI++) {
            const float* tp = cur + ccI * TR * TCP;
            unsigned long long x2[4][3];
#pragma unroll
            for (int r = 0; r < 4; r++) {
                float c0 = tp[(ty * 2 + r) * TCP + tx * 2 + 0];
                float c1 = tp[(ty * 2 + r) * TCP + tx * 2 + 1];
                float c2 = tp[(ty * 2 + r) * TCP + tx * 2 + 2];
                float c3 = tp[(ty * 2 + r) * TCP + tx * 2 + 3];
                x2[r][0] = pack2(c0, c1);
                x2[r][1] = pack2(c1, c2);
                x2[r][2] = pack2(c2, c3);
            }
            const int ci = ci0 + ccI;
#pragma unroll
            for (int co = 0; co < 3; co++) {
                const float* wsp = ws + co * (64 * 9) + ci * 9;
#pragma unroll
                for (int ky = 0; ky < 3; ky++)
#pragma unroll
                    for (int kx = 0; kx < 3; kx++) {
                        float w = wsp[ky * 3 + kx];
                        unsigned long long w2 = pack2(w, w);
#pragma unroll
                        for (int dy = 0; dy < 2; dy++)
                            fma2(acc2[co][dy], w2, x2[dy + ky][kx]);
                    }
            }
        }
        __syncthreads();
    }

#pragma unroll
    for (int co = 0; co < 3; co++) {
        float bias = bf[co];
        float* dp = dst + (((size_t)b * 3 + co) * H) * W;
#pragma unroll
        for (int dy = 0; dy < 2; dy++) {
            float v0, v1;
            unpack2(acc2[co][dy], v0, v1);
            *reinterpret_cast<float2*>(dp + (py0 + dy) * W + px0) =
                make_float2(v0 + bias, v1 + bias);
        }
    }
}

// ---------------------------------------------------------------------------
// launch
// ---------------------------------------------------------------------------
static void* sym(const void* s) {
    void* p = nullptr;
    cudaGetSymbolAddress(&p, s);
    return p;
}

extern "C" void kernel_launch(void* const* d_in, const int* in_sizes, int n_in,
                              void* d_out, int out_size) {
    const float* x     = (const float*)d_in[0];
    const float* style = (const float*)d_in[1];
    const float* w1 = (const float*)d_in[2];
    const float* fw1 = (const float*)d_in[3];
    const float* fb1 = (const float*)d_in[4];
    const float* w2 = (const float*)d_in[5];
    const float* fw2 = (const float*)d_in[6];
    const float* fb2 = (const float*)d_in[7];
    const float* w3 = (const float*)d_in[8];
    const float* fw3 = (const float*)d_in[9];
    const float* fb3 = (const float*)d_in[10];
    const float* w4 = (const float*)d_in[11];
    const float* fw4 = (const float*)d_in[12];
    const float* fb4 = (const float*)d_in[13];
    const float* w5 = (const float*)d_in[14];
    const float* fw5 = (const float*)d_in[15];
    const float* fb5 = (const float*)d_in[16];
    const float* wf = (const float*)d_in[17];
    const float* bf = (const float*)d_in[18];

    float* a1 = (float*)sym(g_a1);
    float* a2 = (float*)sym(g_a2);
    float* a3 = (float*)sym(g_a3);
    float* a4 = (float*)sym(g_a4);
    float* a5 = (float*)sym(g_a5);
    unsigned short* wH1 = (unsigned short*)sym(g_wH1);
    unsigned short* wL1 = (unsigned short*)sym(g_wL1);
    unsigned short* wH2 = (unsigned short*)sym(g_wH2);
    unsigned short* wL2 = (unsigned short*)sym(g_wL2);
    unsigned short* wH3 = (unsigned short*)sym(g_wH3);
    unsigned short* wL3 = (unsigned short*)sym(g_wL3);
    unsigned short* wH4 = (unsigned short*)sym(g_wH4);
    unsigned short* wL4 = (unsigned short*)sym(g_wL4);
    unsigned short* wH5 = (unsigned short*)sym(g_wH5);
    unsigned short* wL5 = (unsigned short*)sym(g_wL5);
    float* s1 = (float*)sym(g_s1);
    float* s2 = (float*)sym(g_s2);
    float* s3 = (float*)sym(g_s3);
    float* s4 = (float*)sym(g_s4);
    float* s5 = (float*)sym(g_s5);

    // dynamic smem: MB=1: (128+128)*72*2*2 = 73728 B; MB=2: (256+128)*72*2*2 = 110592 B
    constexpr int SMEM_MB1 = (2 * 64 + 128) * 72 * 2 * 2;
    constexpr int SMEM_MB2 = (2 * 128 + 128) * 72 * 2 * 2;
    cudaFuncSetAttribute(upconv_mma<512, 256, 8, 8, 1>,
                         cudaFuncAttributeMaxDynamicSharedMemorySize, SMEM_MB1);
    cudaFuncSetAttribute(upconv_mma<256, 128, 16, 16, 1>,
                         cudaFuncAttributeMaxDynamicSharedMemorySize, SMEM_MB1);
    cudaFuncSetAttribute(upconv_mma<128, 64, 32, 32, 2>,
                         cudaFuncAttributeMaxDynamicSharedMemorySize, SMEM_MB2);
    cudaFuncSetAttribute(upconv_mma<64, 64, 64, 64, 2>,
                         cudaFuncAttributeMaxDynamicSharedMemorySize, SMEM_MB2);
    cudaFuncSetAttribute(upconv_mma<64, 64, 128, 128, 2>,
                         cudaFuncAttributeMaxDynamicSharedMemorySize, SMEM_MB2);

    // fused prologue
    {
        int ntot = M1 + M2 + M3 + M4 + M5;
        build_all<<<(ntot + 255) / 256, 256>>>(w1, w2, w3, w4, w5,
                                               wH1, wL1, wH2, wL2, wH3, wL3,
                                               wH4, wL4, wH5, wL5);
        int warps = B_ * 576;
        style_all<<<(warps * 32 + 255) / 256, 256>>>(style,
                                                     fw1, fb1, s1, fw2, fb2, s2,
                                                     fw3, fb3, s3, fw4, fb4, s4,
                                                     fw5, fb5, s5);
    }

    // L1: 512->256, 8x8 -> 16x16   (MB=1, 128 CTAs)
    upconv_mma<512, 256, 8, 8, 1><<<dim3(1, 1, B_ * 4 * 4), 256, SMEM_MB1>>>(x, wH1, wL1, s1, a1);
    // L2: 256->128, 16 -> 32       (MB=1, 256 CTAs)
    upconv_mma<256, 128, 16, 16, 1><<<dim3(2, 2, B_ * 4 * 2), 256, SMEM_MB1>>>(a1, wH2, wL2, s2, a2);
    // L3: 128->64, 32 -> 64        (MB=2, 256 CTAs)
    upconv_mma<128, 64, 32, 32, 2><<<dim3(4, 2, B_ * 4), 256, SMEM_MB2>>>(a2, wH3, wL3, s3, a3);
    // L4: 64->64, 64 -> 128        (MB=2, 1024 CTAs)
    upconv_mma<64, 64, 64, 64, 2><<<dim3(8, 4, B_ * 4), 256, SMEM_MB2>>>(a3, wH4, wL4, s4, a4);
    // L5: 64->64, 128 -> 256       (MB=2, 4096 CTAs)
    upconv_mma<64, 64, 128, 128, 2><<<dim3(16, 8, B_ * 4), 256, SMEM_MB2>>>(a4, wH5, wL5, s5, a5);

    // final conv 64 -> 3 + bias
    final_conv<<<dim3(8, 8, B_), 256>>>(a5, wf, bf, (float*)d_out);
}